// round 9
// baseline (speedup 1.0000x reference)
#include <cuda_runtime.h>
#include <math.h>
#include <stdint.h>

#define BQ 4
#define TQ 8192
#define DQ 1024
#define CQ 64
#define NCQ 128
#define MQ (BQ*TQ)

// Scratch (static device arrays; no allocation allowed)
__device__ float g_v[(size_t)BQ * TQ * DQ];
__device__ float g_reads[(size_t)BQ * TQ * DQ];   // intra part
__device__ float g_p0[(size_t)BQ * TQ * DQ];      // inter partial, e-slice 0
__device__ float g_p1[(size_t)BQ * TQ * DQ];      // inter partial, e-slice 1

__device__ __forceinline__ float sigmoidf_(float x) { return 1.0f / (1.0f + expf(-x)); }
__device__ __forceinline__ uint32_t fu(float x) { return __float_as_uint(x); }
__device__ __forceinline__ float f2tf_f(float x) {
    uint32_t r;
    asm("cvt.rna.tf32.f32 %0, %1;" : "=r"(r) : "f"(x));
    return __uint_as_float(r);
}
// D += A*B, tf32 m16n8k8
__device__ __forceinline__ void mma8(float* d, const uint32_t* a, const uint32_t* b) {
    asm volatile(
        "mma.sync.aligned.m16n8k8.row.col.f32.tf32.tf32.f32 "
        "{%0,%1,%2,%3}, {%4,%5,%6,%7}, {%8,%9}, {%0,%1,%2,%3};\n"
        : "+f"(d[0]), "+f"(d[1]), "+f"(d[2]), "+f"(d[3])
        : "r"(a[0]), "r"(a[1]), "r"(a[2]), "r"(a[3]), "r"(b[0]), "r"(b[1]));
}

// ---------------------------------------------------------------------------
// tf32 GEMM: C = R + alpha*((A+A2+A3) @ B^T)   (A2/A3/R optional)
// A: M x 1024, B: 1024 x 1024, row-major K-contiguous. M = 32768.
// Block tile 128m x 256n, BK=16 double-buffered. 8 warps, warp tile 64x64.
// Smem holds operands in FRAGMENT order so inner loop uses LDS.128/LDS.64:
//   element (m,k): Af[((s*8+mt)*32 + (m&7)*4 + (k&3))*4 + jm*2 + jk]
//   element (n,k): Bf[((s*32+nt)*32 + (n&7)*4 + (k&3))*2 + jk]
//   with s=(k&8)>>3, jk=(k&4)>>2, jm=(m&8)>>3, mt=m>>4, nt=n>>3.
// ---------------------------------------------------------------------------
__global__ void __launch_bounds__(256) gemm_tf32(
    const float* __restrict__ A, const float* __restrict__ Bm,
    const float* __restrict__ A2, const float* __restrict__ A3,
    const float* __restrict__ R, float* __restrict__ C,
    const float* __restrict__ log_alpha_ptr)
{
    __shared__ float Af[2][2048];   // 2 ksec * 8 mt * 32 lane * 4 j
    __shared__ float Bf[2][4096];   // 2 ksec * 32 nt * 32 lane * 2 j

    const int tid = threadIdx.x, lane = tid & 31, wid = tid >> 5;
    const int g = lane >> 2, tg = lane & 3;
    const int wm = wid >> 2;        // 0..1  (64 m rows each)
    const int wn = wid & 3;         // 0..3  (64 n cols each)
    const int m0 = blockIdx.y * 128, n0 = blockIdx.x * 256;

    // A staging coords: row lr (0..127), k offset lk (0 or 8)
    const int lrA = tid >> 1, lkA = (tid & 1) * 8;
    const int ktA = lkA >> 3, mtA = lrA >> 4, jmA = (lrA & 8) >> 3;
    const int baseA = ((ktA * 8 + mtA) * 32 + (lrA & 7) * 4) * 4 + jmA * 2;
    // B staging coords: row n = tid (0..255), all 16 k
    const int ntB = tid >> 3;
    const int baseB0 = ((0 * 32 + ntB) * 32 + (tid & 7) * 4) * 2;
    const int baseB1 = ((1 * 32 + ntB) * 32 + (tid & 7) * 4) * 2;

    const float* Ap  = A  + (size_t)(m0 + lrA) * DQ + lkA;
    const float* Ap2 = A2 ? A2 + (size_t)(m0 + lrA) * DQ + lkA : nullptr;
    const float* Ap3 = A3 ? A3 + (size_t)(m0 + lrA) * DQ + lkA : nullptr;
    const float* Bp  = Bm + (size_t)(n0 + tid) * DQ;

    float av[8];
    float bvv[16];

    // --- prologue: load kt=0 and stage into buf 0 ---
    {
        float4 x0 = *(const float4*)Ap, x1 = *(const float4*)(Ap + 4);
        av[0]=x0.x; av[1]=x0.y; av[2]=x0.z; av[3]=x0.w; av[4]=x1.x; av[5]=x1.y; av[6]=x1.z; av[7]=x1.w;
        if (Ap2) { float4 y0=*(const float4*)Ap2, y1=*(const float4*)(Ap2+4);
            av[0]+=y0.x; av[1]+=y0.y; av[2]+=y0.z; av[3]+=y0.w; av[4]+=y1.x; av[5]+=y1.y; av[6]+=y1.z; av[7]+=y1.w; }
        if (Ap3) { float4 y0=*(const float4*)Ap3, y1=*(const float4*)(Ap3+4);
            av[0]+=y0.x; av[1]+=y0.y; av[2]+=y0.z; av[3]+=y0.w; av[4]+=y1.x; av[5]+=y1.y; av[6]+=y1.z; av[7]+=y1.w; }
        #pragma unroll
        for (int q = 0; q < 4; q++) {
            float4 z = *(const float4*)(Bp + q * 4);
            bvv[q*4+0]=z.x; bvv[q*4+1]=z.y; bvv[q*4+2]=z.z; bvv[q*4+3]=z.w;
        }
        #pragma unroll
        for (int c = 0; c < 4; c++) {
            *(float2*)&Af[0][baseA + c * 4]  = make_float2(f2tf_f(av[c]),      f2tf_f(av[4 + c]));
            *(float2*)&Bf[0][baseB0 + c * 2] = make_float2(f2tf_f(bvv[c]),     f2tf_f(bvv[4 + c]));
            *(float2*)&Bf[0][baseB1 + c * 2] = make_float2(f2tf_f(bvv[8 + c]), f2tf_f(bvv[12 + c]));
        }
    }
    __syncthreads();

    float acc[4][8][4];
    #pragma unroll
    for (int i = 0; i < 4; i++) for (int j = 0; j < 8; j++) for (int q = 0; q < 4; q++) acc[i][j][q] = 0.f;

    const int nK = DQ / 16;  // 64
    int buf = 0;
    for (int kt = 0; kt < nK; kt++) {
        // prefetch next tile into registers
        if (kt < nK - 1) {
            const size_t off = (size_t)(kt + 1) * 16;
            float4 x0 = *(const float4*)(Ap + off), x1 = *(const float4*)(Ap + off + 4);
            av[0]=x0.x; av[1]=x0.y; av[2]=x0.z; av[3]=x0.w; av[4]=x1.x; av[5]=x1.y; av[6]=x1.z; av[7]=x1.w;
            if (Ap2) { float4 y0=*(const float4*)(Ap2+off), y1=*(const float4*)(Ap2+off+4);
                av[0]+=y0.x; av[1]+=y0.y; av[2]+=y0.z; av[3]+=y0.w; av[4]+=y1.x; av[5]+=y1.y; av[6]+=y1.z; av[7]+=y1.w; }
            if (Ap3) { float4 y0=*(const float4*)(Ap3+off), y1=*(const float4*)(Ap3+off+4);
                av[0]+=y0.x; av[1]+=y0.y; av[2]+=y0.z; av[3]+=y0.w; av[4]+=y1.x; av[5]+=y1.y; av[6]+=y1.z; av[7]+=y1.w; }
            #pragma unroll
            for (int q = 0; q < 4; q++) {
                float4 z = *(const float4*)(Bp + off + q * 4);
                bvv[q*4+0]=z.x; bvv[q*4+1]=z.y; bvv[q*4+2]=z.z; bvv[q*4+3]=z.w;
            }
        }
        // compute on current buffer
        #pragma unroll
        for (int s = 0; s < 2; s++) {
            uint32_t a[4][4], bb[8][2];
            #pragma unroll
            for (int mi = 0; mi < 4; mi++) {
                float4 f = *(const float4*)&Af[buf][((s * 8 + wm * 4 + mi) * 32 + lane) * 4];
                a[mi][0] = fu(f.x); a[mi][1] = fu(f.z); a[mi][2] = fu(f.y); a[mi][3] = fu(f.w);
            }
            #pragma unroll
            for (int ni = 0; ni < 8; ni++) {
                float2 f = *(const float2*)&Bf[buf][((s * 32 + wn * 8 + ni) * 32 + lane) * 2];
                bb[ni][0] = fu(f.x); bb[ni][1] = fu(f.y);
            }
            #pragma unroll
            for (int mi = 0; mi < 4; mi++)
                #pragma unroll
                for (int ni = 0; ni < 8; ni++)
                    mma8(acc[mi][ni], a[mi], bb[ni]);
        }
        // stage prefetched tile into other buffer
        if (kt < nK - 1) {
            const int nb = buf ^ 1;
            #pragma unroll
            for (int c = 0; c < 4; c++) {
                *(float2*)&Af[nb][baseA + c * 4]  = make_float2(f2tf_f(av[c]),      f2tf_f(av[4 + c]));
                *(float2*)&Bf[nb][baseB0 + c * 2] = make_float2(f2tf_f(bvv[c]),     f2tf_f(bvv[4 + c]));
                *(float2*)&Bf[nb][baseB1 + c * 2] = make_float2(f2tf_f(bvv[8 + c]), f2tf_f(bvv[12 + c]));
            }
            __syncthreads();
            buf = nb;
        }
    }

    const bool useR = (R != nullptr);
    float alpha = 1.0f;
    if (useR) alpha = expf(*log_alpha_ptr);

    #pragma unroll
    for (int mi = 0; mi < 4; mi++) {
        #pragma unroll
        for (int ni = 0; ni < 8; ni++) {
            const int row0 = m0 + wm * 64 + mi * 16 + g;
            const int col  = n0 + wn * 64 + ni * 8 + 2 * tg;
            float2 v0 = make_float2(acc[mi][ni][0], acc[mi][ni][1]);
            float2 v1 = make_float2(acc[mi][ni][2], acc[mi][ni][3]);
            if (useR) {
                float2 r0 = *(const float2*)&R[(size_t)row0 * DQ + col];
                float2 r1 = *(const float2*)&R[(size_t)(row0 + 8) * DQ + col];
                v0.x = fmaf(alpha, v0.x, r0.x); v0.y = fmaf(alpha, v0.y, r0.y);
                v1.x = fmaf(alpha, v1.x, r1.x); v1.y = fmaf(alpha, v1.y, r1.y);
            }
            *(float2*)&C[(size_t)row0 * DQ + col]       = v0;
            *(float2*)&C[(size_t)(row0 + 8) * DQ + col] = v1;
        }
    }
}

// ---------------------------------------------------------------------------
// Intra-chunk kernel (parallel over all (b,chunk)), fp32.
// ---------------------------------------------------------------------------
__global__ void __launch_bounds__(256) intra_kernel(
    const float* __restrict__ out, const float* __restrict__ decay_ptr)
{
    const int j = blockIdx.x, b = blockIdx.y;
    const float gamma = sigmoidf_(*decay_ptr);
    const float lg = logf(gamma);
    const int tid = threadIdx.x, tx = tid & 15, ty = tid >> 4;
    const int lr = tid >> 2, lk = (tid & 3) << 2;

    __shared__ float SA[16][64];
    __shared__ float SB[16][64];
    __shared__ float Ps[64][64];
    __shared__ float Vs[64][64];

    const float* rbase = out + ((size_t)b * TQ + (size_t)j * CQ) * DQ;
    const int wrow = j * CQ + lr - 1;
    const bool wvalid = (wrow >= 0);
    const float* wptr = out + ((size_t)b * TQ + (size_t)(wvalid ? wrow : 0)) * DQ;

    float acc[4][4];
    #pragma unroll
    for (int i = 0; i < 4; i++) for (int jj = 0; jj < 4; jj++) acc[i][jj] = 0.0f;

    for (int kt = 0; kt < 64; kt++) {
        __syncthreads();
        float4 ra = *(const float4*)(rbase + (size_t)lr * DQ + kt * 16 + lk);
        float4 wa = make_float4(0.f, 0.f, 0.f, 0.f);
        if (wvalid) wa = *(const float4*)(wptr + kt * 16 + lk);
        SA[lk+0][lr] = ra.x; SA[lk+1][lr] = ra.y; SA[lk+2][lr] = ra.z; SA[lk+3][lr] = ra.w;
        SB[lk+0][lr] = wa.x; SB[lk+1][lr] = wa.y; SB[lk+2][lr] = wa.z; SB[lk+3][lr] = wa.w;
        __syncthreads();
        #pragma unroll
        for (int kk = 0; kk < 16; kk++) {
            float af[4], bf[4];
            *(float4*)af = *(const float4*)&SA[kk][ty * 4];
            *(float4*)bf = *(const float4*)&SB[kk][tx * 4];
            #pragma unroll
            for (int i = 0; i < 4; i++)
                #pragma unroll
                for (int jj = 0; jj < 4; jj++)
                    acc[i][jj] = fmaf(af[i], bf[jj], acc[i][jj]);
        }
    }
    __syncthreads();
    #pragma unroll
    for (int i = 0; i < 4; i++)
        #pragma unroll
        for (int jj = 0; jj < 4; jj++) {
            const int c = ty * 4 + i, e = tx * 4 + jj;
            const float msk = (c > e) ? expf(lg * (float)(c - 1 - e)) : 0.0f;
            Ps[c][e] = acc[i][jj] * msk;
        }

    const float* vbase = g_v + ((size_t)b * TQ + (size_t)j * CQ) * DQ;
    float* rd = g_reads + ((size_t)b * TQ + (size_t)j * CQ) * DQ;
    for (int dt = 0; dt < 16; dt++) {
        __syncthreads();
        #pragma unroll
        for (int p = 0; p < 4; p++) {
            const int er = p * 16 + ty;
            *(float4*)&Vs[er][tx * 4] = *(const float4*)(vbase + (size_t)er * DQ + dt * 64 + tx * 4);
        }
        __syncthreads();
        float a2[4][4];
        #pragma unroll
        for (int i = 0; i < 4; i++) for (int jj = 0; jj < 4; jj++) a2[i][jj] = 0.0f;
        #pragma unroll 16
        for (int e = 0; e < 64; e++) {
            float pf[4], vf[4];
            pf[0] = Ps[ty*4+0][e]; pf[1] = Ps[ty*4+1][e]; pf[2] = Ps[ty*4+2][e]; pf[3] = Ps[ty*4+3][e];
            *(float4*)vf = *(const float4*)&Vs[e][tx * 4];
            #pragma unroll
            for (int i = 0; i < 4; i++)
                #pragma unroll
                for (int jj = 0; jj < 4; jj++)
                    a2[i][jj] = fmaf(pf[i], vf[jj], a2[i][jj]);
        }
        #pragma unroll
        for (int i = 0; i < 4; i++) {
            float4 o; o.x = a2[i][0]; o.y = a2[i][1]; o.z = a2[i][2]; o.w = a2[i][3];
            *(float4*)&rd[(size_t)(ty * 4 + i) * DQ + dt * 64 + tx * 4] = o;
        }
    }
}

// ---------------------------------------------------------------------------
// Fused scan kernel — now 512 threads (16 warps) per CTA for 2x latency hiding.
// Grid (16 d-tiles, 2 e-slices, 4 batch) = 128 CTAs.
// CTA keeps W tile [64 d][512 e] in smem for all 128 chunks.
// phase2's w operand = rs shifted by one row (+ prevrow), no w restaging.
// Warp partition:
//   p1: 4 c-tiles (m16) x 4 d-groups (2 n8 each)  -> acc1[2][4]
//   p2: per sec, warp wid owns e-tile wid (m16) x all 8 d n-tiles -> acc2[8][4]
// ---------------------------------------------------------------------------
#define WS_STRIDE 516
#define RS_STRIDE 260
#define US_STRIDE 68
#define SCAN_WORDS (64*WS_STRIDE + 64*RS_STRIDE + 64*US_STRIDE + 520)
#define SCAN_SMEM (SCAN_WORDS * 4)
#define SCAN_THREADS 512

__global__ void __launch_bounds__(SCAN_THREADS) scan_kernel(
    const float* __restrict__ out, const float* __restrict__ decay_ptr,
    float* __restrict__ p0, float* __restrict__ p1)
{
    extern __shared__ float sm[];
    float* Ws = sm;                                  // [64][516]
    float* rs = Ws + 64 * WS_STRIDE;                 // [64][260]
    float* us = rs + 64 * RS_STRIDE;                 // [64][68]
    float* prevrow = us + 64 * US_STRIDE;            // [520] (512 payload)

    const int dt = blockIdx.x, es = blockIdx.y, b = blockIdx.z;
    const int d0g = dt * 64;
    const int e0g = es * 512;
    float* pout = (es == 0) ? p0 : p1;

    const int tid = threadIdx.x, lane = tid & 31, wid = tid >> 5;   // wid 0..15
    const int g = lane >> 2, tg = lane & 3;
    const float gamma = sigmoidf_(*decay_ptr);
    const float lg = logf(gamma);
    const float gC = expf(lg * 64.0f);

    for (int i = tid; i < SCAN_WORDS; i += SCAN_THREADS) sm[i] = 0.0f;

    const float* outb = out + (size_t)b * TQ * DQ;
    const float* vb   = g_v + (size_t)b * TQ * DQ;
    float* pb = pout + (size_t)b * TQ * DQ;

    // p1 warp partition: 4 warps over c (m), 4 groups over d (2 n-tiles each)
    const int wm  = (wid & 3) * 16;
    const int wn2 = (wid >> 2) * 2;

    for (int t = 0; t < NCQ; t++) {
        // ---- stage us[c][d] = v[c,d]*gamma^(63-c), and prevrow (w row for c=0) ----
        #pragma unroll
        for (int i = tid; i < 64 * 16; i += SCAN_THREADS) {
            const int c = i >> 4, x = (i & 15) << 2;
            const float gw = expf(lg * (float)(63 - c));
            float4 vv = *(const float4*)(vb + (size_t)(t * 64 + c) * DQ + d0g + x);
            float* dst = us + c * US_STRIDE + x;
            dst[0] = f2tf_f(vv.x * gw); dst[1] = f2tf_f(vv.y * gw);
            dst[2] = f2tf_f(vv.z * gw); dst[3] = f2tf_f(vv.w * gw);
        }
        if (tid < 256) {
            const int e2 = tid * 2;
            float2 pr = make_float2(0.f, 0.f);
            if (t > 0) pr = *(const float2*)(outb + (size_t)(t * 64 - 1) * DQ + e0g + e2);
            prevrow[e2]     = f2tf_f(pr.x);
            prevrow[e2 + 1] = f2tf_f(pr.y);
        }

        float acc1[2][4];
        #pragma unroll
        for (int n = 0; n < 2; n++) for (int q = 0; q < 4; q++) acc1[n][q] = 0.f;

        #pragma unroll
        for (int sec = 0; sec < 2; sec++) {
            // ---- stage rs[c][e] = r (unshifted), tf32-rounded ----
            #pragma unroll
            for (int i = tid; i < 64 * 64; i += SCAN_THREADS) {
                const int c = i >> 6, x = (i & 63) << 2;
                float4 rv = *(const float4*)(outb + (size_t)(t * 64 + c) * DQ + e0g + sec * 256 + x);
                float* dst = rs + c * RS_STRIDE + x;
                dst[0] = f2tf_f(rv.x); dst[1] = f2tf_f(rv.y);
                dst[2] = f2tf_f(rv.z); dst[3] = f2tf_f(rv.w);
            }
            __syncthreads();

            // ---- phase 1: acc1 += r(sec) @ Ws(sec)^T  (m=c, n=d, k=e) ----
            if (t > 0) {
                for (int k = 0; k < 32; k++) {
                    uint32_t a[4];
                    a[0] = fu(rs[(wm + g    ) * RS_STRIDE + k * 8 + tg    ]);
                    a[1] = fu(rs[(wm + g + 8) * RS_STRIDE + k * 8 + tg    ]);
                    a[2] = fu(rs[(wm + g    ) * RS_STRIDE + k * 8 + tg + 4]);
                    a[3] = fu(rs[(wm + g + 8) * RS_STRIDE + k * 8 + tg + 4]);
                    #pragma unroll
                    for (int n = 0; n < 2; n++) {
                        const int d = (wn2 + n) * 8 + g;
                        uint32_t bb[2];
                        bb[0] = fu(Ws[d * WS_STRIDE + sec * 256 + k * 8 + tg    ]);
                        bb[1] = fu(Ws[d * WS_STRIDE + sec * 256 + k * 8 + tg + 4]);
                        mma8(acc1[n], a, bb);
                    }
                }
            }

            // ---- phase 2: acc2 = w(sec)^T @ u  (m=e, n=d, k=c), w = rs shifted ----
            // warp wid owns e-tile wid (16 e rows) of this 256-col sec.
            float acc2[8][4];
            #pragma unroll
            for (int n = 0; n < 8; n++) for (int q = 0; q < 4; q++) acc2[n][q] = 0.f;
            const float* prsec = prevrow + sec * 256;
            const int ew = wid * 16;
            for (int kk = 0; kk < 8; kk++) {
                const int c0 = kk * 8 + tg - 1;          // k = tg row (shifted)
                const int c1 = kk * 8 + tg + 3;          // k = tg+4 row (shifted)
                const float* r0 = (c0 >= 0) ? (rs + c0 * RS_STRIDE) : prsec;
                const float* r1 = rs + c1 * RS_STRIDE;
                uint32_t a[4], bb[8][2];
                a[0] = fu(r0[ew + g    ]);
                a[1] = fu(r0[ew + g + 8]);
                a[2] = fu(r1[ew + g    ]);
                a[3] = fu(r1[ew + g + 8]);
                #pragma unroll
                for (int n = 0; n < 8; n++) {
                    bb[n][0] = fu(us[(kk * 8 + tg    ) * US_STRIDE + n * 8 + g]);
                    bb[n][1] = fu(us[(kk * 8 + tg + 4) * US_STRIDE + n * 8 + g]);
                }
                #pragma unroll
                for (int n = 0; n < 8; n++)
                    mma8(acc2[n], a, bb[n]);
            }
            __syncthreads();   // all p1 reads of Ws(sec) + all rs reads done

            // ---- RMW Ws(sec): W = gC*W + acc2 ; C frag is [m=e][n=d] ----
            {
                const int e = sec * 256 + ew;
                #pragma unroll
                for (int n = 0; n < 8; n++) {
                    const int d = n * 8 + 2 * tg;
                    float* w00 = &Ws[(size_t)d       * WS_STRIDE + e + g];
                    float* w01 = &Ws[(size_t)(d + 1) * WS_STRIDE + e + g];
                    float* w10 = &Ws[(size_t)d       * WS_STRIDE + e + g + 8];
                    float* w11 = &Ws[(size_t)(d + 1) * WS_STRIDE + e + g + 8];
                    *w00 = fmaf(gC, *w00, acc2[n][0]);
                    *w01 = fmaf(gC, *w01, acc2[n][1]);
                    *w10 = fmaf(gC, *w10, acc2[n][2]);
                    *w11 = fmaf(gC, *w11, acc2[n][3]);
                }
            }
        }

        // ---- store inter partial (gamma^c scaled), or zeros at t=0 ----
        if (t > 0) {
            const int c0 = wm + g, c1 = wm + g + 8;
            const float s0 = expf(lg * (float)c0), s1 = expf(lg * (float)c1);
            #pragma unroll
            for (int n = 0; n < 2; n++) {
                const int dg = d0g + (wn2 + n) * 8 + 2 * tg;
                float2 v0 = make_float2(acc1[n][0] * s0, acc1[n][1] * s0);
                float2 v1 = make_float2(acc1[n][2] * s1, acc1[n][3] * s1);
                *(float2*)(pb + (size_t)(t * 64 + c0) * DQ + dg) = v0;
                *(float2*)(pb + (size_t)(t * 64 + c1) * DQ + dg) = v1;
            }
        } else {
            #pragma unroll
            for (int i = tid; i < 64 * 16; i += SCAN_THREADS) {
                const int c = i >> 4, x = (i & 15) << 2;
                *(float4*)(pb + (size_t)c * DQ + d0g + x) = make_float4(0.f, 0.f, 0.f, 0.f);
            }
        }
        __syncthreads();   // W RMW + staging buffers quiesced before next chunk
    }
}

// ---------------------------------------------------------------------------
extern "C" void kernel_launch(void* const* d_in, const int* in_sizes, int n_in,
                              void* d_out, int out_size)
{
    const float* out_in    = (const float*)d_in[0];
    const float* W_write   = (const float*)d_in[1];
    const float* W_read    = (const float*)d_in[2];
    const float* decay     = (const float*)d_in[3];
    const float* log_alpha = (const float*)d_in[4];
    float* outp = (float*)d_out;

    static bool attr_set = false;
    if (!attr_set) {
        cudaFuncSetAttribute(scan_kernel, cudaFuncAttributeMaxDynamicSharedMemorySize, SCAN_SMEM);
        attr_set = true;
    }

    void *pv = nullptr, *pr = nullptr, *pp0 = nullptr, *pp1 = nullptr;
    cudaGetSymbolAddress(&pv, g_v);
    cudaGetSymbolAddress(&pr, g_reads);
    cudaGetSymbolAddress(&pp0, g_p0);
    cudaGetSymbolAddress(&pp1, g_p1);

    dim3 ggemm(DQ / 256, MQ / 128);  // (4, 256)

    // 1) v = out @ W_write^T  (tf32)
    gemm_tf32<<<ggemm, 256>>>(out_in, W_write, nullptr, nullptr, nullptr, (float*)pv, nullptr);

    // 2) intra part of reads -> g_reads (parallel over chunks)
    intra_kernel<<<dim3(NCQ, BQ), 256>>>(out_in, decay);

    // 3) whole sequential scan in ONE kernel -> inter partials g_p0/g_p1
    scan_kernel<<<dim3(16, 2, BQ), SCAN_THREADS, SCAN_SMEM>>>(out_in, decay, (float*)pp0, (float*)pp1);

    // 4) output = out + alpha * ((g_reads + g_p0 + g_p1) @ W_read^T)
    gemm_tf32<<<ggemm, 256>>>((const float*)pr, W_read, (const float*)pp0, (const float*)pp1,
                              out_in, outp, log_alpha);
}

// round 10
// speedup vs baseline: 1.0794x; 1.0794x over previous
#include <cuda_runtime.h>
#include <math.h>
#include <stdint.h>

#define BQ 4
#define TQ 8192
#define DQ 1024
#define CQ 64
#define NCQ 128
#define MQ (BQ*TQ)

// Scratch (static device arrays; no allocation allowed)
__device__ float g_v[(size_t)BQ * TQ * DQ];
__device__ float g_reads[(size_t)BQ * TQ * DQ];   // intra part
__device__ float g_p0[(size_t)BQ * TQ * DQ];      // inter partial, e-slice 0
__device__ float g_p1[(size_t)BQ * TQ * DQ];      // inter partial, e-slice 1

__device__ __forceinline__ float sigmoidf_(float x) { return 1.0f / (1.0f + expf(-x)); }
__device__ __forceinline__ uint32_t fu(float x) { return __float_as_uint(x); }
__device__ __forceinline__ float f2tf_f(float x) {
    uint32_t r;
    asm("cvt.rna.tf32.f32 %0, %1;" : "=r"(r) : "f"(x));
    return __uint_as_float(r);
}
// D += A*B, tf32 m16n8k8
__device__ __forceinline__ void mma8(float* d, const uint32_t* a, const uint32_t* b) {
    asm volatile(
        "mma.sync.aligned.m16n8k8.row.col.f32.tf32.tf32.f32 "
        "{%0,%1,%2,%3}, {%4,%5,%6,%7}, {%8,%9}, {%0,%1,%2,%3};\n"
        : "+f"(d[0]), "+f"(d[1]), "+f"(d[2]), "+f"(d[3])
        : "r"(a[0]), "r"(a[1]), "r"(a[2]), "r"(a[3]), "r"(b[0]), "r"(b[1]));
}

// ---------------------------------------------------------------------------
// tf32 GEMM: C = R + alpha*((A+A2+A3) @ B^T)   (A2/A3/R optional)
// A: M x 1024, B: 1024 x 1024, row-major K-contiguous. M = 32768.
// Block tile 128m x 256n, BK=16 double-buffered. 8 warps, warp tile 64x64.
// Smem holds operands in FRAGMENT order so inner loop uses LDS.128/LDS.64.
// ---------------------------------------------------------------------------
__global__ void __launch_bounds__(256) gemm_tf32(
    const float* __restrict__ A, const float* __restrict__ Bm,
    const float* __restrict__ A2, const float* __restrict__ A3,
    const float* __restrict__ R, float* __restrict__ C,
    const float* __restrict__ log_alpha_ptr)
{
    __shared__ float Af[2][2048];   // 2 ksec * 8 mt * 32 lane * 4 j
    __shared__ float Bf[2][4096];   // 2 ksec * 32 nt * 32 lane * 2 j

    const int tid = threadIdx.x, lane = tid & 31, wid = tid >> 5;
    const int g = lane >> 2, tg = lane & 3;
    const int wm = wid >> 2;        // 0..1  (64 m rows each)
    const int wn = wid & 3;         // 0..3  (64 n cols each)
    const int m0 = blockIdx.y * 128, n0 = blockIdx.x * 256;

    // A staging coords: row lr (0..127), k offset lk (0 or 8)
    const int lrA = tid >> 1, lkA = (tid & 1) * 8;
    const int ktA = lkA >> 3, mtA = lrA >> 4, jmA = (lrA & 8) >> 3;
    const int baseA = ((ktA * 8 + mtA) * 32 + (lrA & 7) * 4) * 4 + jmA * 2;
    // B staging coords: row n = tid (0..255), all 16 k
    const int ntB = tid >> 3;
    const int baseB0 = ((0 * 32 + ntB) * 32 + (tid & 7) * 4) * 2;
    const int baseB1 = ((1 * 32 + ntB) * 32 + (tid & 7) * 4) * 2;

    const float* Ap  = A  + (size_t)(m0 + lrA) * DQ + lkA;
    const float* Ap2 = A2 ? A2 + (size_t)(m0 + lrA) * DQ + lkA : nullptr;
    const float* Ap3 = A3 ? A3 + (size_t)(m0 + lrA) * DQ + lkA : nullptr;
    const float* Bp  = Bm + (size_t)(n0 + tid) * DQ;

    float av[8];
    float bvv[16];

    // --- prologue: load kt=0 and stage into buf 0 ---
    {
        float4 x0 = *(const float4*)Ap, x1 = *(const float4*)(Ap + 4);
        av[0]=x0.x; av[1]=x0.y; av[2]=x0.z; av[3]=x0.w; av[4]=x1.x; av[5]=x1.y; av[6]=x1.z; av[7]=x1.w;
        if (Ap2) { float4 y0=*(const float4*)Ap2, y1=*(const float4*)(Ap2+4);
            av[0]+=y0.x; av[1]+=y0.y; av[2]+=y0.z; av[3]+=y0.w; av[4]+=y1.x; av[5]+=y1.y; av[6]+=y1.z; av[7]+=y1.w; }
        if (Ap3) { float4 y0=*(const float4*)Ap3, y1=*(const float4*)(Ap3+4);
            av[0]+=y0.x; av[1]+=y0.y; av[2]+=y0.z; av[3]+=y0.w; av[4]+=y1.x; av[5]+=y1.y; av[6]+=y1.z; av[7]+=y1.w; }
        #pragma unroll
        for (int q = 0; q < 4; q++) {
            float4 z = *(const float4*)(Bp + q * 4);
            bvv[q*4+0]=z.x; bvv[q*4+1]=z.y; bvv[q*4+2]=z.z; bvv[q*4+3]=z.w;
        }
        #pragma unroll
        for (int c = 0; c < 4; c++) {
            *(float2*)&Af[0][baseA + c * 4]  = make_float2(f2tf_f(av[c]),      f2tf_f(av[4 + c]));
            *(float2*)&Bf[0][baseB0 + c * 2] = make_float2(f2tf_f(bvv[c]),     f2tf_f(bvv[4 + c]));
            *(float2*)&Bf[0][baseB1 + c * 2] = make_float2(f2tf_f(bvv[8 + c]), f2tf_f(bvv[12 + c]));
        }
    }
    __syncthreads();

    float acc[4][8][4];
    #pragma unroll
    for (int i = 0; i < 4; i++) for (int j = 0; j < 8; j++) for (int q = 0; q < 4; q++) acc[i][j][q] = 0.f;

    const int nK = DQ / 16;  // 64
    int buf = 0;
    for (int kt = 0; kt < nK; kt++) {
        // prefetch next tile into registers
        if (kt < nK - 1) {
            const size_t off = (size_t)(kt + 1) * 16;
            float4 x0 = *(const float4*)(Ap + off), x1 = *(const float4*)(Ap + off + 4);
            av[0]=x0.x; av[1]=x0.y; av[2]=x0.z; av[3]=x0.w; av[4]=x1.x; av[5]=x1.y; av[6]=x1.z; av[7]=x1.w;
            if (Ap2) { float4 y0=*(const float4*)(Ap2+off), y1=*(const float4*)(Ap2+off+4);
                av[0]+=y0.x; av[1]+=y0.y; av[2]+=y0.z; av[3]+=y0.w; av[4]+=y1.x; av[5]+=y1.y; av[6]+=y1.z; av[7]+=y1.w; }
            if (Ap3) { float4 y0=*(const float4*)(Ap3+off), y1=*(const float4*)(Ap3+off+4);
                av[0]+=y0.x; av[1]+=y0.y; av[2]+=y0.z; av[3]+=y0.w; av[4]+=y1.x; av[5]+=y1.y; av[6]+=y1.z; av[7]+=y1.w; }
            #pragma unroll
            for (int q = 0; q < 4; q++) {
                float4 z = *(const float4*)(Bp + off + q * 4);
                bvv[q*4+0]=z.x; bvv[q*4+1]=z.y; bvv[q*4+2]=z.z; bvv[q*4+3]=z.w;
            }
        }
        // compute on current buffer
        #pragma unroll
        for (int s = 0; s < 2; s++) {
            uint32_t a[4][4], bb[8][2];
            #pragma unroll
            for (int mi = 0; mi < 4; mi++) {
                float4 f = *(const float4*)&Af[buf][((s * 8 + wm * 4 + mi) * 32 + lane) * 4];
                a[mi][0] = fu(f.x); a[mi][1] = fu(f.z); a[mi][2] = fu(f.y); a[mi][3] = fu(f.w);
            }
            #pragma unroll
            for (int ni = 0; ni < 8; ni++) {
                float2 f = *(const float2*)&Bf[buf][((s * 32 + wn * 8 + ni) * 32 + lane) * 2];
                bb[ni][0] = fu(f.x); bb[ni][1] = fu(f.y);
            }
            #pragma unroll
            for (int mi = 0; mi < 4; mi++)
                #pragma unroll
                for (int ni = 0; ni < 8; ni++)
                    mma8(acc[mi][ni], a[mi], bb[ni]);
        }
        // stage prefetched tile into other buffer
        if (kt < nK - 1) {
            const int nb = buf ^ 1;
            #pragma unroll
            for (int c = 0; c < 4; c++) {
                *(float2*)&Af[nb][baseA + c * 4]  = make_float2(f2tf_f(av[c]),      f2tf_f(av[4 + c]));
                *(float2*)&Bf[nb][baseB0 + c * 2] = make_float2(f2tf_f(bvv[c]),     f2tf_f(bvv[4 + c]));
                *(float2*)&Bf[nb][baseB1 + c * 2] = make_float2(f2tf_f(bvv[8 + c]), f2tf_f(bvv[12 + c]));
            }
            __syncthreads();
            buf = nb;
        }
    }

    const bool useR = (R != nullptr);
    float alpha = 1.0f;
    if (useR) alpha = expf(*log_alpha_ptr);

    #pragma unroll
    for (int mi = 0; mi < 4; mi++) {
        #pragma unroll
        for (int ni = 0; ni < 8; ni++) {
            const int row0 = m0 + wm * 64 + mi * 16 + g;
            const int col  = n0 + wn * 64 + ni * 8 + 2 * tg;
            float2 v0 = make_float2(acc[mi][ni][0], acc[mi][ni][1]);
            float2 v1 = make_float2(acc[mi][ni][2], acc[mi][ni][3]);
            if (useR) {
                float2 r0 = *(const float2*)&R[(size_t)row0 * DQ + col];
                float2 r1 = *(const float2*)&R[(size_t)(row0 + 8) * DQ + col];
                v0.x = fmaf(alpha, v0.x, r0.x); v0.y = fmaf(alpha, v0.y, r0.y);
                v1.x = fmaf(alpha, v1.x, r1.x); v1.y = fmaf(alpha, v1.y, r1.y);
            }
            *(float2*)&C[(size_t)row0 * DQ + col]       = v0;
            *(float2*)&C[(size_t)(row0 + 8) * DQ + col] = v1;
        }
    }
}

// ---------------------------------------------------------------------------
// Intra-chunk kernel (parallel over all (b,chunk)), fp32.
// ---------------------------------------------------------------------------
__global__ void __launch_bounds__(256) intra_kernel(
    const float* __restrict__ out, const float* __restrict__ decay_ptr)
{
    const int j = blockIdx.x, b = blockIdx.y;
    const float gamma = sigmoidf_(*decay_ptr);
    const float lg = logf(gamma);
    const int tid = threadIdx.x, tx = tid & 15, ty = tid >> 4;
    const int lr = tid >> 2, lk = (tid & 3) << 2;

    __shared__ float SA[16][64];
    __shared__ float SB[16][64];
    __shared__ float Ps[64][64];
    __shared__ float Vs[64][64];

    const float* rbase = out + ((size_t)b * TQ + (size_t)j * CQ) * DQ;
    const int wrow = j * CQ + lr - 1;
    const bool wvalid = (wrow >= 0);
    const float* wptr = out + ((size_t)b * TQ + (size_t)(wvalid ? wrow : 0)) * DQ;

    float acc[4][4];
    #pragma unroll
    for (int i = 0; i < 4; i++) for (int jj = 0; jj < 4; jj++) acc[i][jj] = 0.0f;

    for (int kt = 0; kt < 64; kt++) {
        __syncthreads();
        float4 ra = *(const float4*)(rbase + (size_t)lr * DQ + kt * 16 + lk);
        float4 wa = make_float4(0.f, 0.f, 0.f, 0.f);
        if (wvalid) wa = *(const float4*)(wptr + kt * 16 + lk);
        SA[lk+0][lr] = ra.x; SA[lk+1][lr] = ra.y; SA[lk+2][lr] = ra.z; SA[lk+3][lr] = ra.w;
        SB[lk+0][lr] = wa.x; SB[lk+1][lr] = wa.y; SB[lk+2][lr] = wa.z; SB[lk+3][lr] = wa.w;
        __syncthreads();
        #pragma unroll
        for (int kk = 0; kk < 16; kk++) {
            float af[4], bf[4];
            *(float4*)af = *(const float4*)&SA[kk][ty * 4];
            *(float4*)bf = *(const float4*)&SB[kk][tx * 4];
            #pragma unroll
            for (int i = 0; i < 4; i++)
                #pragma unroll
                for (int jj = 0; jj < 4; jj++)
                    acc[i][jj] = fmaf(af[i], bf[jj], acc[i][jj]);
        }
    }
    __syncthreads();
    #pragma unroll
    for (int i = 0; i < 4; i++)
        #pragma unroll
        for (int jj = 0; jj < 4; jj++) {
            const int c = ty * 4 + i, e = tx * 4 + jj;
            const float msk = (c > e) ? expf(lg * (float)(c - 1 - e)) : 0.0f;
            Ps[c][e] = acc[i][jj] * msk;
        }

    const float* vbase = g_v + ((size_t)b * TQ + (size_t)j * CQ) * DQ;
    float* rd = g_reads + ((size_t)b * TQ + (size_t)j * CQ) * DQ;
    for (int dt = 0; dt < 16; dt++) {
        __syncthreads();
        #pragma unroll
        for (int p = 0; p < 4; p++) {
            const int er = p * 16 + ty;
            *(float4*)&Vs[er][tx * 4] = *(const float4*)(vbase + (size_t)er * DQ + dt * 64 + tx * 4);
        }
        __syncthreads();
        float a2[4][4];
        #pragma unroll
        for (int i = 0; i < 4; i++) for (int jj = 0; jj < 4; jj++) a2[i][jj] = 0.0f;
        #pragma unroll 16
        for (int e = 0; e < 64; e++) {
            float pf[4], vf[4];
            pf[0] = Ps[ty*4+0][e]; pf[1] = Ps[ty*4+1][e]; pf[2] = Ps[ty*4+2][e]; pf[3] = Ps[ty*4+3][e];
            *(float4*)vf = *(const float4*)&Vs[e][tx * 4];
            #pragma unroll
            for (int i = 0; i < 4; i++)
                #pragma unroll
                for (int jj = 0; jj < 4; jj++)
                    a2[i][jj] = fmaf(pf[i], vf[jj], a2[i][jj]);
        }
        #pragma unroll
        for (int i = 0; i < 4; i++) {
            float4 o; o.x = a2[i][0]; o.y = a2[i][1]; o.z = a2[i][2]; o.w = a2[i][3];
            *(float4*)&rd[(size_t)(ty * 4 + i) * DQ + dt * 64 + tx * 4] = o;
        }
    }
}

// ---------------------------------------------------------------------------
// Fused scan kernel (256 threads, R8 partition) with:
//  - sec1 rs tile prefetched into registers at chunk start (LDG latency hidden
//    behind sec0 compute), stored to smem at sec1
//  - all per-thread-constant expf hoisted out of the chunk loop
// Grid (16 d-tiles, 2 e-slices, 4 batch) = 128 CTAs.
// ---------------------------------------------------------------------------
#define WS_STRIDE 516
#define RS_STRIDE 260
#define US_STRIDE 68
#define SCAN_WORDS (64*WS_STRIDE + 64*RS_STRIDE + 64*US_STRIDE + 520)
#define SCAN_SMEM (SCAN_WORDS * 4)

__global__ void __launch_bounds__(256) scan_kernel(
    const float* __restrict__ out, const float* __restrict__ decay_ptr,
    float* __restrict__ p0, float* __restrict__ p1)
{
    extern __shared__ float sm[];
    float* Ws = sm;                                  // [64][516]
    float* rs = Ws + 64 * WS_STRIDE;                 // [64][260]
    float* us = rs + 64 * RS_STRIDE;                 // [64][68]
    float* prevrow = us + 64 * US_STRIDE;            // [520] (512 payload)

    const int dt = blockIdx.x, es = blockIdx.y, b = blockIdx.z;
    const int d0g = dt * 64;
    const int e0g = es * 512;
    float* pout = (es == 0) ? p0 : p1;

    const int tid = threadIdx.x, lane = tid & 31, wid = tid >> 5;
    const int g = lane >> 2, tg = lane & 3;
    const float gamma = sigmoidf_(*decay_ptr);
    const float lg = logf(gamma);
    const float gC = expf(lg * 64.0f);

    for (int i = tid; i < SCAN_WORDS; i += 256) sm[i] = 0.0f;

    const float* outb = out + (size_t)b * TQ * DQ;
    const float* vb   = g_v + (size_t)b * TQ * DQ;
    float* pb = pout + (size_t)b * TQ * DQ;

    // p1 warp partition: 4 warps over c (m), 2 groups over d (4 n-tiles each)
    const int wm  = (wid & 3) * 16;
    const int wn4 = (wid >> 2) * 4;

    // hoisted per-thread constants (chunk-invariant)
    float gw_it[4];
    #pragma unroll
    for (int it = 0; it < 4; it++) {
        const int c = (tid + it * 256) >> 4;
        gw_it[it] = expf(lg * (float)(63 - c));
    }
    const float s0 = expf(lg * (float)(wm + g));
    const float s1 = expf(lg * (float)(wm + g + 8));

    for (int t = 0; t < NCQ; t++) {
        // ---- stage us[c][d] = v[c,d]*gamma^(63-c), prevrow, rs(sec0); prefetch rs(sec1) ----
        #pragma unroll
        for (int it = 0; it < 4; it++) {
            const int i = tid + it * 256;
            const int c = i >> 4, x = (i & 15) << 2;
            float4 vv = *(const float4*)(vb + (size_t)(t * 64 + c) * DQ + d0g + x);
            float* dst = us + c * US_STRIDE + x;
            const float gw = gw_it[it];
            dst[0] = f2tf_f(vv.x * gw); dst[1] = f2tf_f(vv.y * gw);
            dst[2] = f2tf_f(vv.z * gw); dst[3] = f2tf_f(vv.w * gw);
        }
        {
            const int e2 = tid * 2;
            float2 pr = make_float2(0.f, 0.f);
            if (t > 0) pr = *(const float2*)(outb + (size_t)(t * 64 - 1) * DQ + e0g + e2);
            prevrow[e2]     = f2tf_f(pr.x);
            prevrow[e2 + 1] = f2tf_f(pr.y);
        }
        #pragma unroll
        for (int it = 0; it < 16; it++) {
            const int i = tid + it * 256;
            const int c = i >> 6, x = (i & 63) << 2;
            float4 rv = *(const float4*)(outb + (size_t)(t * 64 + c) * DQ + e0g + x);
            float* dst = rs + c * RS_STRIDE + x;
            dst[0] = f2tf_f(rv.x); dst[1] = f2tf_f(rv.y);
            dst[2] = f2tf_f(rv.z); dst[3] = f2tf_f(rv.w);
        }
        float4 r1v[16];
        #pragma unroll
        for (int it = 0; it < 16; it++) {
            const int i = tid + it * 256;
            const int c = i >> 6, x = (i & 63) << 2;
            r1v[it] = *(const float4*)(outb + (size_t)(t * 64 + c) * DQ + e0g + 256 + x);
        }

        float acc1[4][4];
        #pragma unroll
        for (int n = 0; n < 4; n++) for (int q = 0; q < 4; q++) acc1[n][q] = 0.f;

        #pragma unroll
        for (int sec = 0; sec < 2; sec++) {
            if (sec == 1) {
                // store prefetched rs(sec1) from registers (no LDG latency here)
                #pragma unroll
                for (int it = 0; it < 16; it++) {
                    const int i = tid + it * 256;
                    const int c = i >> 6, x = (i & 63) << 2;
                    float* dst = rs + c * RS_STRIDE + x;
                    dst[0] = f2tf_f(r1v[it].x); dst[1] = f2tf_f(r1v[it].y);
                    dst[2] = f2tf_f(r1v[it].z); dst[3] = f2tf_f(r1v[it].w);
                }
            }
            __syncthreads();

            // ---- phase 1: acc1 += r(sec) @ Ws(sec)^T  (m=c, n=d, k=e) ----
            if (t > 0) {
                for (int k = 0; k < 32; k++) {
                    uint32_t a[4];
                    a[0] = fu(rs[(wm + g    ) * RS_STRIDE + k * 8 + tg    ]);
                    a[1] = fu(rs[(wm + g + 8) * RS_STRIDE + k * 8 + tg    ]);
                    a[2] = fu(rs[(wm + g    ) * RS_STRIDE + k * 8 + tg + 4]);
                    a[3] = fu(rs[(wm + g + 8) * RS_STRIDE + k * 8 + tg + 4]);
                    #pragma unroll
                    for (int n = 0; n < 4; n++) {
                        const int d = (wn4 + n) * 8 + g;
                        uint32_t bb[2];
                        bb[0] = fu(Ws[d * WS_STRIDE + sec * 256 + k * 8 + tg    ]);
                        bb[1] = fu(Ws[d * WS_STRIDE + sec * 256 + k * 8 + tg + 4]);
                        mma8(acc1[n], a, bb);
                    }
                }
            }

            // ---- phase 2: acc2 = w(sec)^T @ u  (m=e, n=d, k=c), w = rs shifted ----
            float acc2[2][8][4];
            #pragma unroll
            for (int m = 0; m < 2; m++) for (int n = 0; n < 8; n++) for (int q = 0; q < 4; q++) acc2[m][n][q] = 0.f;
            const float* prsec = prevrow + sec * 256;
            for (int kk = 0; kk < 8; kk++) {
                const int c0 = kk * 8 + tg - 1;          // k = tg row (shifted)
                const int c1 = kk * 8 + tg + 3;          // k = tg+4 row (shifted)
                const float* r0 = (c0 >= 0) ? (rs + c0 * RS_STRIDE) : prsec;
                const float* r1 = rs + c1 * RS_STRIDE;
                uint32_t a[2][4], bb[8][2];
                #pragma unroll
                for (int m = 0; m < 2; m++) {
                    const int e = (wid * 2 + m) * 16;
                    a[m][0] = fu(r0[e + g    ]);
                    a[m][1] = fu(r0[e + g + 8]);
                    a[m][2] = fu(r1[e + g    ]);
                    a[m][3] = fu(r1[e + g + 8]);
                }
                #pragma unroll
                for (int n = 0; n < 8; n++) {
                    bb[n][0] = fu(us[(kk * 8 + tg    ) * US_STRIDE + n * 8 + g]);
                    bb[n][1] = fu(us[(kk * 8 + tg + 4) * US_STRIDE + n * 8 + g]);
                }
                #pragma unroll
                for (int m = 0; m < 2; m++)
                    #pragma unroll
                    for (int n = 0; n < 8; n++)
                        mma8(acc2[m][n], a[m], bb[n]);
            }
            __syncthreads();   // all p1 reads of Ws(sec) + all rs reads done

            // ---- RMW Ws(sec): W = gC*W + acc2 ; C frag is [m=e][n=d] ----
            #pragma unroll
            for (int m = 0; m < 2; m++) {
                const int e = sec * 256 + (wid * 2 + m) * 16;
                #pragma unroll
                for (int n = 0; n < 8; n++) {
                    const int d = n * 8 + 2 * tg;
                    float* w00 = &Ws[(size_t)d       * WS_STRIDE + e + g];
                    float* w01 = &Ws[(size_t)(d + 1) * WS_STRIDE + e + g];
                    float* w10 = &Ws[(size_t)d       * WS_STRIDE + e + g + 8];
                    float* w11 = &Ws[(size_t)(d + 1) * WS_STRIDE + e + g + 8];
                    *w00 = fmaf(gC, *w00, acc2[m][n][0]);
                    *w01 = fmaf(gC, *w01, acc2[m][n][1]);
                    *w10 = fmaf(gC, *w10, acc2[m][n][2]);
                    *w11 = fmaf(gC, *w11, acc2[m][n][3]);
                }
            }
        }

        // ---- store inter partial (gamma^c scaled), or zeros at t=0 ----
        if (t > 0) {
            const int c0 = wm + g, c1 = wm + g + 8;
            #pragma unroll
            for (int n = 0; n < 4; n++) {
                const int dg = d0g + (wn4 + n) * 8 + 2 * tg;
                float2 v0 = make_float2(acc1[n][0] * s0, acc1[n][1] * s0);
                float2 v1 = make_float2(acc1[n][2] * s1, acc1[n][3] * s1);
                *(float2*)(pb + (size_t)(t * 64 + c0) * DQ + dg) = v0;
                *(float2*)(pb + (size_t)(t * 64 + c1) * DQ + dg) = v1;
            }
        } else {
            #pragma unroll
            for (int it = 0; it < 4; it++) {
                const int i = tid + it * 256;
                const int c = i >> 4, x = (i & 15) << 2;
                *(float4*)(pb + (size_t)c * DQ + d0g + x) = make_float4(0.f, 0.f, 0.f, 0.f);
            }
        }
        __syncthreads();   // W RMW + staging buffers quiesced before next chunk
    }
}

// ---------------------------------------------------------------------------
extern "C" void kernel_launch(void* const* d_in, const int* in_sizes, int n_in,
                              void* d_out, int out_size)
{
    const float* out_in    = (const float*)d_in[0];
    const float* W_write   = (const float*)d_in[1];
    const float* W_read    = (const float*)d_in[2];
    const float* decay     = (const float*)d_in[3];
    const float* log_alpha = (const float*)d_in[4];
    float* outp = (float*)d_out;

    static bool attr_set = false;
    if (!attr_set) {
        cudaFuncSetAttribute(scan_kernel, cudaFuncAttributeMaxDynamicSharedMemorySize, SCAN_SMEM);
        attr_set = true;
    }

    void *pv = nullptr, *pr = nullptr, *pp0 = nullptr, *pp1 = nullptr;
    cudaGetSymbolAddress(&pv, g_v);
    cudaGetSymbolAddress(&pr, g_reads);
    cudaGetSymbolAddress(&pp0, g_p0);
    cudaGetSymbolAddress(&pp1, g_p1);

    dim3 ggemm(DQ / 256, MQ / 128);  // (4, 256)

    // 1) v = out @ W_write^T  (tf32)
    gemm_tf32<<<ggemm, 256>>>(out_in, W_write, nullptr, nullptr, nullptr, (float*)pv, nullptr);

    // 2) intra part of reads -> g_reads (parallel over chunks)
    intra_kernel<<<dim3(NCQ, BQ), 256>>>(out_in, decay);

    // 3) whole sequential scan in ONE kernel -> inter partials g_p0/g_p1
    scan_kernel<<<dim3(16, 2, BQ), 256, SCAN_SMEM>>>(out_in, decay, (float*)pp0, (float*)pp1);

    // 4) output = out + alpha * ((g_reads + g_p0 + g_p1) @ W_read^T)
    gemm_tf32<<<ggemm, 256>>>((const float*)pr, W_read, (const float*)pp0, (const float*)pp1,
                              out_in, outp, log_alpha);
}